// round 2
// baseline (speedup 1.0000x reference)
#include <cuda_runtime.h>
#include <cuda_fp16.h>
#include <stdint.h>

#define TILE    256
#define THREADS 512
#define XPAD    72   // halves per row: 64 data + 8 pad (conflict-free mma frag loads)

__device__ __forceinline__ void mma16816(float c[4], const uint32_t a[4],
                                         uint32_t b0, uint32_t b1) {
    asm volatile(
        "mma.sync.aligned.m16n8k16.row.col.f32.f16.f16.f32 "
        "{%0,%1,%2,%3}, {%4,%5,%6,%7}, {%8,%9}, {%0,%1,%2,%3};"
        : "+f"(c[0]), "+f"(c[1]), "+f"(c[2]), "+f"(c[3])
        : "r"(a[0]), "r"(a[1]), "r"(a[2]), "r"(a[3]), "r"(b0), "r"(b1));
}

__global__ __launch_bounds__(THREADS, 4)
void neumf_fused(const int* __restrict__ user, const int* __restrict__ item,
                 const float* __restrict__ mf_u, const float* __restrict__ mf_i,
                 const float* __restrict__ mlp_u, const float* __restrict__ mlp_i,
                 const float* __restrict__ W1, const float* __restrict__ b1,
                 const float* __restrict__ W2, const float* __restrict__ b2,
                 const float* __restrict__ Wo, const float* __restrict__ bo,
                 float* __restrict__ out, int n)
{
    __shared__ __half Xs[TILE][XPAD];   // 36864 B : concat mlp embeddings, fp16
    __shared__ __half Ws1[64][XPAD];    //  9216 B : W1 transposed [n][k]
    __shared__ __half Ws2[32][XPAD];    //  4608 B : W2 transposed [n][k]
    __shared__ float  b1s[64], b2s[32], Wos[48];
    __shared__ float  mfd[TILE];
    __shared__ int    us[TILE], is[TILE];
    __shared__ float  bos;

    const int t    = threadIdx.x;
    const int base = blockIdx.x * TILE;

    // ---- Phase 0: weights + indices -> smem ----
    for (int idx = t; idx < 64 * 64; idx += THREADS) {
        int k = idx >> 6, nn = idx & 63;
        Ws1[nn][k] = __float2half_rn(W1[idx]);
    }
    for (int idx = t; idx < 64 * 32; idx += THREADS) {
        int k = idx >> 5, nn = idx & 31;
        Ws2[nn][k] = __float2half_rn(W2[idx]);
    }
    if (t < 64) b1s[t] = b1[t];
    if (t < 32) b2s[t] = b2[t];
    if (t < 48) Wos[t] = Wo[t];
    if (t == 0) bos = bo[0];
    if (t < TILE) {
        int gi = base + t;
        us[t] = (gi < n) ? user[gi] : 0;
    } else {
        int s  = t - TILE;
        int gi = base + s;
        is[s] = (gi < n) ? item[gi] : 0;
    }
    __syncthreads();

    // ---- Phase 1a: MLP embedding gather, COALESCED: 8 lanes per 128B row ----
    {
        const int lane8 = t & 7;       // position within row (float4 index)
        const int rowg  = t >> 3;      // 0..63
        #pragma unroll
        for (int it = 0; it < 8; it++) {
            int r  = rowg + it * 64;   // 0..511 : 256 samples x {user,item}
            int s  = r >> 1, h = r & 1;
            int gi = base + s;
            uint2* dst = (uint2*)&Xs[s][h * 32 + lane8 * 4];
            if (gi < n) {
                int row = h ? is[s] : us[s];
                const float4* src =
                    (const float4*)((h ? mlp_i : mlp_u) + (size_t)row * 32) + lane8;
                float4 v = *src;
                __half2 lo = __floats2half2_rn(v.x, v.y);
                __half2 hi = __floats2half2_rn(v.z, v.w);
                uint2 pk; pk.x = *(uint32_t*)&lo; pk.y = *(uint32_t*)&hi;
                *dst = pk;
            } else {
                *dst = make_uint2(0u, 0u);
            }
        }
    }

    // ---- Phase 1b: GMF dot, COALESCED: 4 lanes per 64B row, quad shfl reduce ----
    {
        const int chunk = t & 3;       // float4 index within mf row
        const int sg    = t >> 2;      // 0..127
        #pragma unroll
        for (int p = 0; p < 2; p++) {
            int s  = sg + p * 128;
            int gi = base + s;
            float acc = 0.f;
            if (gi < n) {
                float4 a = ((const float4*)(mf_u + (size_t)us[s] * 16))[chunk];
                float4 c = ((const float4*)(mf_i + (size_t)is[s] * 16))[chunk];
                acc = a.x * c.x * __ldg(&Wo[4 * chunk + 0])
                    + a.y * c.y * __ldg(&Wo[4 * chunk + 1])
                    + a.z * c.z * __ldg(&Wo[4 * chunk + 2])
                    + a.w * c.w * __ldg(&Wo[4 * chunk + 3]);
            }
            acc += __shfl_xor_sync(0xFFFFFFFFu, acc, 1);
            acc += __shfl_xor_sync(0xFFFFFFFFu, acc, 2);
            if (chunk == 0) mfd[s] = acc;
        }
    }
    __syncthreads();

    // ---- Phase 2: per-warp 16-row GEMM pipeline (16 warps x 16 rows = 256) ----
    const int warp  = t >> 5;
    const int lane  = t & 31;
    const int rbase = warp * 16;
    const int lr    = lane >> 2;     // 0..7
    const int lc    = lane & 3;      // 0..3

    // GEMM1: X[16,64] @ W1[64,64] -> acc1 (8 n-tiles)
    float acc1[8][4];
    #pragma unroll
    for (int nn = 0; nn < 8; nn++)
        #pragma unroll
        for (int j = 0; j < 4; j++) acc1[nn][j] = 0.f;

    #pragma unroll
    for (int kt = 0; kt < 4; kt++) {
        uint32_t a[4];
        a[0] = *(const uint32_t*)&Xs[rbase + lr    ][kt * 16     + 2 * lc];
        a[1] = *(const uint32_t*)&Xs[rbase + lr + 8][kt * 16     + 2 * lc];
        a[2] = *(const uint32_t*)&Xs[rbase + lr    ][kt * 16 + 8 + 2 * lc];
        a[3] = *(const uint32_t*)&Xs[rbase + lr + 8][kt * 16 + 8 + 2 * lc];
        #pragma unroll
        for (int nn = 0; nn < 8; nn++) {
            uint32_t bb0 = *(const uint32_t*)&Ws1[nn * 8 + lr][kt * 16     + 2 * lc];
            uint32_t bb1 = *(const uint32_t*)&Ws1[nn * 8 + lr][kt * 16 + 8 + 2 * lc];
            mma16816(acc1[nn], a, bb0, bb1);
        }
    }

    // Epilogue1: +b1, ReLU, fp16 -> GEMM2 A-fragments (pure register permute)
    uint32_t A2[4][4];
    #pragma unroll
    for (int nn = 0; nn < 8; nn++) {
        int   col = nn * 8 + 2 * lc;
        float bx = b1s[col], by = b1s[col + 1];
        float v0 = fmaxf(acc1[nn][0] + bx, 0.f);
        float v1 = fmaxf(acc1[nn][1] + by, 0.f);
        float v2 = fmaxf(acc1[nn][2] + bx, 0.f);
        float v3 = fmaxf(acc1[nn][3] + by, 0.f);
        __half2 lo = __floats2half2_rn(v0, v1);
        __half2 hi = __floats2half2_rn(v2, v3);
        int kt2 = nn >> 1, g = nn & 1;
        A2[kt2][g * 2 + 0] = *(uint32_t*)&lo;
        A2[kt2][g * 2 + 1] = *(uint32_t*)&hi;
    }

    // GEMM2: H1[16,64] @ W2[64,32] -> acc2 (4 n-tiles)
    float acc2[4][4];
    #pragma unroll
    for (int nn = 0; nn < 4; nn++)
        #pragma unroll
        for (int j = 0; j < 4; j++) acc2[nn][j] = 0.f;

    #pragma unroll
    for (int kt = 0; kt < 4; kt++) {
        #pragma unroll
        for (int nn = 0; nn < 4; nn++) {
            uint32_t bb0 = *(const uint32_t*)&Ws2[nn * 8 + lr][kt * 16     + 2 * lc];
            uint32_t bb1 = *(const uint32_t*)&Ws2[nn * 8 + lr][kt * 16 + 8 + 2 * lc];
            mma16816(acc2[nn], A2[kt], bb0, bb1);
        }
    }

    // Epilogue2: +b2, ReLU, dot Wo[16:48], quad reduce, add GMF + bo
    float s_lo = 0.f, s_hi = 0.f;
    #pragma unroll
    for (int nn = 0; nn < 4; nn++) {
        int   col = nn * 8 + 2 * lc;
        float bx = b2s[col], by = b2s[col + 1];
        float wx = Wos[16 + col], wy = Wos[16 + col + 1];
        s_lo += fmaxf(acc2[nn][0] + bx, 0.f) * wx + fmaxf(acc2[nn][1] + by, 0.f) * wy;
        s_hi += fmaxf(acc2[nn][2] + bx, 0.f) * wx + fmaxf(acc2[nn][3] + by, 0.f) * wy;
    }
    s_lo += __shfl_xor_sync(0xFFFFFFFFu, s_lo, 1);
    s_lo += __shfl_xor_sync(0xFFFFFFFFu, s_lo, 2);
    s_hi += __shfl_xor_sync(0xFFFFFFFFu, s_hi, 1);
    s_hi += __shfl_xor_sync(0xFFFFFFFFu, s_hi, 2);

    if (lc == 0) {
        int r0 = rbase + lr, r1 = rbase + lr + 8;
        if (base + r0 < n) out[base + r0] = s_lo + mfd[r0] + bos;
        if (base + r1 < n) out[base + r1] = s_hi + mfd[r1] + bos;
    }
}

extern "C" void kernel_launch(void* const* d_in, const int* in_sizes, int n_in,
                              void* d_out, int out_size) {
    const int*   user  = (const int*)  d_in[0];
    const int*   item  = (const int*)  d_in[1];
    const float* mf_u  = (const float*)d_in[2];
    const float* mf_i  = (const float*)d_in[3];
    const float* mlp_u = (const float*)d_in[4];
    const float* mlp_i = (const float*)d_in[5];
    const float* W1    = (const float*)d_in[6];
    const float* b1    = (const float*)d_in[7];
    const float* W2    = (const float*)d_in[8];
    const float* b2    = (const float*)d_in[9];
    const float* Wo    = (const float*)d_in[10];
    const float* bo    = (const float*)d_in[11];
    float* out = (float*)d_out;

    int n = in_sizes[0];
    int blocks = (n + TILE - 1) / TILE;
    neumf_fused<<<blocks, THREADS>>>(user, item, mf_u, mf_i, mlp_u, mlp_i,
                                     W1, b1, W2, b2, Wo, bo, out, n);
}

// round 3
// speedup vs baseline: 1.2329x; 1.2329x over previous
#include <cuda_runtime.h>
#include <cuda_fp16.h>
#include <stdint.h>

#define TILE    128
#define THREADS 256
#define XPAD    72   // halves per row: 64 data + 8 pad (conflict-free mma frag loads)

__device__ __forceinline__ void mma16816(float c[4], const uint32_t a[4],
                                         uint32_t b0, uint32_t b1) {
    asm volatile(
        "mma.sync.aligned.m16n8k16.row.col.f32.f16.f16.f32 "
        "{%0,%1,%2,%3}, {%4,%5,%6,%7}, {%8,%9}, {%0,%1,%2,%3};"
        : "+f"(c[0]), "+f"(c[1]), "+f"(c[2]), "+f"(c[3])
        : "r"(a[0]), "r"(a[1]), "r"(a[2]), "r"(a[3]), "r"(b0), "r"(b1));
}

__global__ __launch_bounds__(THREADS, 3)   // 85-reg cap: fits ~79-reg pipeline, no spills
void neumf_fused(const int* __restrict__ user, const int* __restrict__ item,
                 const float* __restrict__ mf_u, const float* __restrict__ mf_i,
                 const float* __restrict__ mlp_u, const float* __restrict__ mlp_i,
                 const float* __restrict__ W1, const float* __restrict__ b1,
                 const float* __restrict__ W2, const float* __restrict__ b2,
                 const float* __restrict__ Wo, const float* __restrict__ bo,
                 float* __restrict__ out, int n)
{
    __shared__ __half Xs[TILE][XPAD];   // 18432 B : concat mlp embeddings, fp16
    __shared__ __half Ws1[64][XPAD];    //  9216 B : W1 transposed [n][k]
    __shared__ __half Ws2[32][XPAD];    //  4608 B : W2 transposed [n][k]
    __shared__ float  b1s[64], b2s[32], Wos[48];
    __shared__ float  mfd[TILE];
    __shared__ int    us[TILE], is[TILE];
    __shared__ float  bos;

    const int t    = threadIdx.x;
    const int base = blockIdx.x * TILE;

    // ---- Phase 0: weights + indices -> smem ----
    for (int idx = t; idx < 64 * 64; idx += THREADS) {
        int k = idx >> 6, nn = idx & 63;
        Ws1[nn][k] = __float2half_rn(W1[idx]);
    }
    for (int idx = t; idx < 64 * 32; idx += THREADS) {
        int k = idx >> 5, nn = idx & 31;
        Ws2[nn][k] = __float2half_rn(W2[idx]);
    }
    if (t < 64) b1s[t] = b1[t];
    if (t < 32) b2s[t] = b2[t];
    if (t < 48) Wos[t] = Wo[t];
    if (t == 0) bos = bo[0];
    if (t < TILE) {
        int gi = base + t;
        us[t] = (gi < n) ? user[gi] : 0;
    } else if (t < 2 * TILE) {
        int s  = t - TILE;
        int gi = base + s;
        is[s] = (gi < n) ? item[gi] : 0;
    }
    __syncthreads();

    // ---- Phase 1a: MLP embedding gather, COALESCED: 8 lanes per 128B row ----
    {
        const int lane8 = t & 7;       // float4 index within embedding row
        const int rowg  = t >> 3;      // 0..31
        #pragma unroll
        for (int it = 0; it < 8; it++) {
            int r  = rowg + it * 32;   // 0..255 : 128 samples x {user,item}
            int s  = r >> 1, h = r & 1;
            int gi = base + s;
            uint2* dst = (uint2*)&Xs[s][h * 32 + lane8 * 4];
            if (gi < n) {
                int row = h ? is[s] : us[s];
                const float4* src =
                    (const float4*)((h ? mlp_i : mlp_u) + (size_t)row * 32) + lane8;
                float4 v = *src;
                __half2 lo = __floats2half2_rn(v.x, v.y);
                __half2 hi = __floats2half2_rn(v.z, v.w);
                uint2 pk; pk.x = *(uint32_t*)&lo; pk.y = *(uint32_t*)&hi;
                *dst = pk;
            } else {
                *dst = make_uint2(0u, 0u);
            }
        }
    }

    // ---- Phase 1b: GMF dot, COALESCED: 4 lanes per 64B row, quad shfl reduce ----
    {
        const int chunk = t & 3;       // float4 index within mf row
        const int sg    = t >> 2;      // 0..63
        #pragma unroll
        for (int p = 0; p < 2; p++) {
            int s  = sg + p * 64;
            int gi = base + s;
            float acc = 0.f;
            if (gi < n) {
                float4 a = ((const float4*)(mf_u + (size_t)us[s] * 16))[chunk];
                float4 c = ((const float4*)(mf_i + (size_t)is[s] * 16))[chunk];
                acc = a.x * c.x * __ldg(&Wo[4 * chunk + 0])
                    + a.y * c.y * __ldg(&Wo[4 * chunk + 1])
                    + a.z * c.z * __ldg(&Wo[4 * chunk + 2])
                    + a.w * c.w * __ldg(&Wo[4 * chunk + 3]);
            }
            acc += __shfl_xor_sync(0xFFFFFFFFu, acc, 1);
            acc += __shfl_xor_sync(0xFFFFFFFFu, acc, 2);
            if (chunk == 0) mfd[s] = acc;
        }
    }
    __syncthreads();

    // ---- Phase 2: per-warp 16-row GEMM pipeline (8 warps x 16 rows = 128) ----
    const int warp  = t >> 5;
    const int lane  = t & 31;
    const int rbase = warp * 16;
    const int lr    = lane >> 2;     // 0..7
    const int lc    = lane & 3;      // 0..3

    // GEMM1: X[16,64] @ W1[64,64] -> acc1 (8 n-tiles)
    float acc1[8][4];
    #pragma unroll
    for (int nn = 0; nn < 8; nn++)
        #pragma unroll
        for (int j = 0; j < 4; j++) acc1[nn][j] = 0.f;

    #pragma unroll
    for (int kt = 0; kt < 4; kt++) {
        uint32_t a[4];
        a[0] = *(const uint32_t*)&Xs[rbase + lr    ][kt * 16     + 2 * lc];
        a[1] = *(const uint32_t*)&Xs[rbase + lr + 8][kt * 16     + 2 * lc];
        a[2] = *(const uint32_t*)&Xs[rbase + lr    ][kt * 16 + 8 + 2 * lc];
        a[3] = *(const uint32_t*)&Xs[rbase + lr + 8][kt * 16 + 8 + 2 * lc];
        #pragma unroll
        for (int nn = 0; nn < 8; nn++) {
            uint32_t bb0 = *(const uint32_t*)&Ws1[nn * 8 + lr][kt * 16     + 2 * lc];
            uint32_t bb1 = *(const uint32_t*)&Ws1[nn * 8 + lr][kt * 16 + 8 + 2 * lc];
            mma16816(acc1[nn], a, bb0, bb1);
        }
    }

    // Epilogue1: +b1, ReLU, fp16 -> GEMM2 A-fragments (pure register permute)
    uint32_t A2[4][4];
    #pragma unroll
    for (int nn = 0; nn < 8; nn++) {
        int   col = nn * 8 + 2 * lc;
        float bx = b1s[col], by = b1s[col + 1];
        float v0 = fmaxf(acc1[nn][0] + bx, 0.f);
        float v1 = fmaxf(acc1[nn][1] + by, 0.f);
        float v2 = fmaxf(acc1[nn][2] + bx, 0.f);
        float v3 = fmaxf(acc1[nn][3] + by, 0.f);
        __half2 lo = __floats2half2_rn(v0, v1);
        __half2 hi = __floats2half2_rn(v2, v3);
        int kt2 = nn >> 1, g = nn & 1;
        A2[kt2][g * 2 + 0] = *(uint32_t*)&lo;
        A2[kt2][g * 2 + 1] = *(uint32_t*)&hi;
    }

    // GEMM2: H1[16,64] @ W2[64,32] -> acc2 (4 n-tiles)
    float acc2[4][4];
    #pragma unroll
    for (int nn = 0; nn < 4; nn++)
        #pragma unroll
        for (int j = 0; j < 4; j++) acc2[nn][j] = 0.f;

    #pragma unroll
    for (int kt = 0; kt < 4; kt++) {
        #pragma unroll
        for (int nn = 0; nn < 4; nn++) {
            uint32_t bb0 = *(const uint32_t*)&Ws2[nn * 8 + lr][kt * 16     + 2 * lc];
            uint32_t bb1 = *(const uint32_t*)&Ws2[nn * 8 + lr][kt * 16 + 8 + 2 * lc];
            mma16816(acc2[nn], A2[kt], bb0, bb1);
        }
    }

    // Epilogue2: +b2, ReLU, dot Wo[16:48], quad reduce, add GMF + bo
    float s_lo = 0.f, s_hi = 0.f;
    #pragma unroll
    for (int nn = 0; nn < 4; nn++) {
        int   col = nn * 8 + 2 * lc;
        float bx = b2s[col], by = b2s[col + 1];
        float wx = Wos[16 + col], wy = Wos[16 + col + 1];
        s_lo += fmaxf(acc2[nn][0] + bx, 0.f) * wx + fmaxf(acc2[nn][1] + by, 0.f) * wy;
        s_hi += fmaxf(acc2[nn][2] + bx, 0.f) * wx + fmaxf(acc2[nn][3] + by, 0.f) * wy;
    }
    s_lo += __shfl_xor_sync(0xFFFFFFFFu, s_lo, 1);
    s_lo += __shfl_xor_sync(0xFFFFFFFFu, s_lo, 2);
    s_hi += __shfl_xor_sync(0xFFFFFFFFu, s_hi, 1);
    s_hi += __shfl_xor_sync(0xFFFFFFFFu, s_hi, 2);

    if (lc == 0) {
        int r0 = rbase + lr, r1 = rbase + lr + 8;
        if (base + r0 < n) out[base + r0] = s_lo + mfd[r0] + bos;
        if (base + r1 < n) out[base + r1] = s_hi + mfd[r1] + bos;
    }
}

extern "C" void kernel_launch(void* const* d_in, const int* in_sizes, int n_in,
                              void* d_out, int out_size) {
    const int*   user  = (const int*)  d_in[0];
    const int*   item  = (const int*)  d_in[1];
    const float* mf_u  = (const float*)d_in[2];
    const float* mf_i  = (const float*)d_in[3];
    const float* mlp_u = (const float*)d_in[4];
    const float* mlp_i = (const float*)d_in[5];
    const float* W1    = (const float*)d_in[6];
    const float* b1    = (const float*)d_in[7];
    const float* W2    = (const float*)d_in[8];
    const float* b2    = (const float*)d_in[9];
    const float* Wo    = (const float*)d_in[10];
    const float* bo    = (const float*)d_in[11];
    float* out = (float*)d_out;

    int n = in_sizes[0];
    int blocks = (n + TILE - 1) / TILE;
    neumf_fused<<<blocks, THREADS>>>(user, item, mf_u, mf_i, mlp_u, mlp_i,
                                     W1, b1, W2, b2, Wo, bo, out, n);
}

// round 4
// speedup vs baseline: 1.8469x; 1.4981x over previous
#include <cuda_runtime.h>
#include <cuda_fp16.h>
#include <stdint.h>

#define TILE    128
#define THREADS 256
#define XPAD    72   // halves per row: 64 data + 8 pad (conflict-free mma frag loads)

__device__ __forceinline__ void mma16816(float c[4], const uint32_t a[4],
                                         uint32_t b0, uint32_t b1) {
    asm volatile(
        "mma.sync.aligned.m16n8k16.row.col.f32.f16.f16.f32 "
        "{%0,%1,%2,%3}, {%4,%5,%6,%7}, {%8,%9}, {%0,%1,%2,%3};"
        : "+f"(c[0]), "+f"(c[1]), "+f"(c[2]), "+f"(c[3])
        : "r"(a[0]), "r"(a[1]), "r"(a[2]), "r"(a[3]), "r"(b0), "r"(b1));
}

__global__ __launch_bounds__(THREADS, 3)   // 85-reg cap: fits pipeline, no spills
void neumf_fused(const int* __restrict__ user, const int* __restrict__ item,
                 const float* __restrict__ mf_u, const float* __restrict__ mf_i,
                 const float* __restrict__ mlp_u, const float* __restrict__ mlp_i,
                 const float* __restrict__ W1, const float* __restrict__ b1,
                 const float* __restrict__ W2, const float* __restrict__ b2,
                 const float* __restrict__ Wo, const float* __restrict__ bo,
                 float* __restrict__ out, int n)
{
    __shared__ __half Xs[TILE][XPAD];   // 18432 B : concat mlp embeddings, fp16
    __shared__ __half Ws1[64][XPAD];    //  9216 B : W1 transposed [n][k]
    __shared__ __half Ws2[32][XPAD];    //  4608 B : W2 transposed [n][k]
    __shared__ float  b1s[64], b2s[32], Wos[48];
    __shared__ float  mfd[TILE];
    __shared__ int    us[TILE], is[TILE];
    __shared__ float  bos;

    const int t    = threadIdx.x;
    const int base = blockIdx.x * TILE;

    // ---- Phase 0: weights + indices -> smem ----
    for (int idx = t; idx < 64 * 64; idx += THREADS) {
        int k = idx >> 6, nn = idx & 63;
        Ws1[nn][k] = __float2half_rn(W1[idx]);
    }
    for (int idx = t; idx < 64 * 32; idx += THREADS) {
        int k = idx >> 5, nn = idx & 31;
        Ws2[nn][k] = __float2half_rn(W2[idx]);
    }
    if (t < 64) b1s[t] = b1[t];
    if (t < 32) b2s[t] = b2[t];
    if (t < 48) Wos[t] = Wo[t];
    if (t == 0) bos = bo[0];
    if (t < TILE) {
        int gi = base + t;
        us[t] = (gi < n) ? user[gi] : 0;    // clamp OOB to row 0: loads stay safe
    } else if (t < 2 * TILE) {
        int s  = t - TILE;
        int gi = base + s;
        is[s] = (gi < n) ? item[gi] : 0;
    }
    __syncthreads();

    // ---- Phase 1a: MLP gather, branch-free + explicitly batched (MLP_p1=8) ----
    {
        const int lane8 = t & 7;       // float4 index within embedding row
        const int rowg  = t >> 3;      // 0..31
        float4 v[8];
        #pragma unroll
        for (int it = 0; it < 8; it++) {
            int r   = rowg + it * 32;          // 0..255 : 128 samples x {user,item}
            int s   = r >> 1, h = r & 1;
            int row = h ? is[s] : us[s];
            const float* tbl = h ? mlp_i : mlp_u;
            v[it] = ((const float4*)(tbl + (size_t)row * 32))[lane8];
        }
        #pragma unroll
        for (int it = 0; it < 8; it++) {
            int r = rowg + it * 32;
            int s = r >> 1, h = r & 1;
            __half2 lo = __floats2half2_rn(v[it].x, v[it].y);
            __half2 hi = __floats2half2_rn(v[it].z, v[it].w);
            uint2 pk; pk.x = *(uint32_t*)&lo; pk.y = *(uint32_t*)&hi;
            *(uint2*)&Xs[s][h * 32 + lane8 * 4] = pk;
        }
    }

    // ---- Phase 1b: GMF dot, branch-free batched loads, quad shfl reduce ----
    {
        const int chunk = t & 3;       // float4 index within mf row
        const int sg    = t >> 2;      // 0..63
        const int s0 = sg, s1 = sg + 64;
        float4 a0 = ((const float4*)(mf_u + (size_t)us[s0] * 16))[chunk];
        float4 c0 = ((const float4*)(mf_i + (size_t)is[s0] * 16))[chunk];
        float4 a1 = ((const float4*)(mf_u + (size_t)us[s1] * 16))[chunk];
        float4 c1 = ((const float4*)(mf_i + (size_t)is[s1] * 16))[chunk];
        float w0 = Wos[4 * chunk + 0], w1 = Wos[4 * chunk + 1];
        float w2 = Wos[4 * chunk + 2], w3 = Wos[4 * chunk + 3];
        float acc0 = a0.x * c0.x * w0 + a0.y * c0.y * w1
                   + a0.z * c0.z * w2 + a0.w * c0.w * w3;
        float acc1 = a1.x * c1.x * w0 + a1.y * c1.y * w1
                   + a1.z * c1.z * w2 + a1.w * c1.w * w3;
        acc0 += __shfl_xor_sync(0xFFFFFFFFu, acc0, 1);
        acc0 += __shfl_xor_sync(0xFFFFFFFFu, acc0, 2);
        acc1 += __shfl_xor_sync(0xFFFFFFFFu, acc1, 1);
        acc1 += __shfl_xor_sync(0xFFFFFFFFu, acc1, 2);
        if (chunk == 0) { mfd[s0] = acc0; mfd[s1] = acc1; }
    }
    __syncthreads();

    // ---- Phase 2: per-warp 16-row GEMM pipeline (8 warps x 16 rows = 128) ----
    const int warp  = t >> 5;
    const int lane  = t & 31;
    const int rbase = warp * 16;
    const int lr    = lane >> 2;     // 0..7
    const int lc    = lane & 3;      // 0..3

    // GEMM1: X[16,64] @ W1[64,64] -> acc1 (8 n-tiles)
    float acc1[8][4];
    #pragma unroll
    for (int nn = 0; nn < 8; nn++)
        #pragma unroll
        for (int j = 0; j < 4; j++) acc1[nn][j] = 0.f;

    #pragma unroll
    for (int kt = 0; kt < 4; kt++) {
        uint32_t a[4];
        a[0] = *(const uint32_t*)&Xs[rbase + lr    ][kt * 16     + 2 * lc];
        a[1] = *(const uint32_t*)&Xs[rbase + lr + 8][kt * 16     + 2 * lc];
        a[2] = *(const uint32_t*)&Xs[rbase + lr    ][kt * 16 + 8 + 2 * lc];
        a[3] = *(const uint32_t*)&Xs[rbase + lr + 8][kt * 16 + 8 + 2 * lc];
        #pragma unroll
        for (int nn = 0; nn < 8; nn++) {
            uint32_t bb0 = *(const uint32_t*)&Ws1[nn * 8 + lr][kt * 16     + 2 * lc];
            uint32_t bb1 = *(const uint32_t*)&Ws1[nn * 8 + lr][kt * 16 + 8 + 2 * lc];
            mma16816(acc1[nn], a, bb0, bb1);
        }
    }

    // Epilogue1: +b1, ReLU, fp16 -> GEMM2 A-fragments (pure register permute)
    uint32_t A2[4][4];
    #pragma unroll
    for (int nn = 0; nn < 8; nn++) {
        int   col = nn * 8 + 2 * lc;
        float bx = b1s[col], by = b1s[col + 1];
        float v0 = fmaxf(acc1[nn][0] + bx, 0.f);
        float v1 = fmaxf(acc1[nn][1] + by, 0.f);
        float v2 = fmaxf(acc1[nn][2] + bx, 0.f);
        float v3 = fmaxf(acc1[nn][3] + by, 0.f);
        __half2 lo = __floats2half2_rn(v0, v1);
        __half2 hi = __floats2half2_rn(v2, v3);
        int kt2 = nn >> 1, g = nn & 1;
        A2[kt2][g * 2 + 0] = *(uint32_t*)&lo;
        A2[kt2][g * 2 + 1] = *(uint32_t*)&hi;
    }

    // GEMM2: H1[16,64] @ W2[64,32] -> acc2 (4 n-tiles)
    float acc2[4][4];
    #pragma unroll
    for (int nn = 0; nn < 4; nn++)
        #pragma unroll
        for (int j = 0; j < 4; j++) acc2[nn][j] = 0.f;

    #pragma unroll
    for (int kt = 0; kt < 4; kt++) {
        #pragma unroll
        for (int nn = 0; nn < 4; nn++) {
            uint32_t bb0 = *(const uint32_t*)&Ws2[nn * 8 + lr][kt * 16     + 2 * lc];
            uint32_t bb1 = *(const uint32_t*)&Ws2[nn * 8 + lr][kt * 16 + 8 + 2 * lc];
            mma16816(acc2[nn], A2[kt], bb0, bb1);
        }
    }

    // Epilogue2: +b2, ReLU, dot Wo[16:48], quad reduce, add GMF + bo
    float s_lo = 0.f, s_hi = 0.f;
    #pragma unroll
    for (int nn = 0; nn < 4; nn++) {
        int   col = nn * 8 + 2 * lc;
        float bx = b2s[col], by = b2s[col + 1];
        float wx = Wos[16 + col], wy = Wos[16 + col + 1];
        s_lo += fmaxf(acc2[nn][0] + bx, 0.f) * wx + fmaxf(acc2[nn][1] + by, 0.f) * wy;
        s_hi += fmaxf(acc2[nn][2] + bx, 0.f) * wx + fmaxf(acc2[nn][3] + by, 0.f) * wy;
    }
    s_lo += __shfl_xor_sync(0xFFFFFFFFu, s_lo, 1);
    s_lo += __shfl_xor_sync(0xFFFFFFFFu, s_lo, 2);
    s_hi += __shfl_xor_sync(0xFFFFFFFFu, s_hi, 1);
    s_hi += __shfl_xor_sync(0xFFFFFFFFu, s_hi, 2);

    if (lc == 0) {
        int r0 = rbase + lr, r1 = rbase + lr + 8;
        if (base + r0 < n) out[base + r0] = s_lo + mfd[r0] + bos;
        if (base + r1 < n) out[base + r1] = s_hi + mfd[r1] + bos;
    }
}

extern "C" void kernel_launch(void* const* d_in, const int* in_sizes, int n_in,
                              void* d_out, int out_size) {
    const int*   user  = (const int*)  d_in[0];
    const int*   item  = (const int*)  d_in[1];
    const float* mf_u  = (const float*)d_in[2];
    const float* mf_i  = (const float*)d_in[3];
    const float* mlp_u = (const float*)d_in[4];
    const float* mlp_i = (const float*)d_in[5];
    const float* W1    = (const float*)d_in[6];
    const float* b1    = (const float*)d_in[7];
    const float* W2    = (const float*)d_in[8];
    const float* b2    = (const float*)d_in[9];
    const float* Wo    = (const float*)d_in[10];
    const float* bo    = (const float*)d_in[11];
    float* out = (float*)d_out;

    int n = in_sizes[0];
    int blocks = (n + TILE - 1) / TILE;
    neumf_fused<<<blocks, THREADS>>>(user, item, mf_u, mf_i, mlp_u, mlp_i,
                                     W1, b1, W2, b2, Wo, bo, out, n);
}